// round 12
// baseline (speedup 1.0000x reference)
#include <cuda_runtime.h>
#include <cuda_fp16.h>
#include <cstdint>

#define N_Q   16384
#define DIMS  64
#define K_CB  8192
#define MT    128            // queries per CTA
#define NT    128            // codewords per tile
#define NTILES (K_CB / NT)   // 64
#define THREADS 640          // 16 MMA warps + 4 scalar warps
#define N_MMA  96            // cols handled by tensor cores
#define TAU 2.5f

// padded f16 row: 64 elems + 8 pad = 72 elems = 144 bytes
#define ROWB 144
#define TERM_BYTES (128 * ROWB)      // 18432 per tile (128 rows)
#define STAGE (TERM_BYTES + 512)     // tile + csq = 18944

// shared memory layout (bytes)
#define SM_B     0                       // 4 stages x 18944 = 75776
#define SM_A     75776                   // 18432
#define SM_CAND  94208                   // 128 q x 52 slots x 8B = 53248
#define SM_BESTK 147456                  // 128 ints
#define SMEM_TOTAL 147968

__device__ __half g_enc_h[N_Q * DIMS];
__device__ __half g_cb_h[K_CB * DIMS];
__device__ __align__(16) float g_csq[K_CB];

// ---------------- helpers ----------------
__device__ __forceinline__ uint32_t smem_u32(const void* p) {
    uint32_t a;
    asm("{ .reg .u64 t; cvta.to.shared.u64 t, %1; cvt.u32.u64 %0, t; }" : "=r"(a) : "l"(p));
    return a;
}
#define CP16(d, s)  asm volatile("cp.async.cg.shared.global [%0], [%1], 16;" :: "r"(d), "l"(s))
#define CP_COMMIT() asm volatile("cp.async.commit_group;" ::: "memory")
#define CP_WAIT2()  asm volatile("cp.async.wait_group 2;" ::: "memory")

__device__ __forceinline__ void ldsm_x4(uint32_t* r, uint32_t addr) {
    asm volatile("ldmatrix.sync.aligned.m8n8.x4.shared.b16 {%0,%1,%2,%3}, [%4];"
                 : "=r"(r[0]), "=r"(r[1]), "=r"(r[2]), "=r"(r[3]) : "r"(addr));
}
__device__ __forceinline__ void ldsm_x2(uint32_t* r, uint32_t addr) {
    asm volatile("ldmatrix.sync.aligned.m8n8.x2.shared.b16 {%0,%1}, [%2];"
                 : "=r"(r[0]), "=r"(r[1]) : "r"(addr));
}
// f16 x f16 -> f16 accumulate
__device__ __forceinline__ void mma16816_h(uint32_t* c, const uint32_t* a, const uint32_t* b) {
    asm volatile("mma.sync.aligned.m16n8k16.row.col.f16.f16.f16.f16 "
                 "{%0,%1}, {%2,%3,%4,%5}, {%6,%7}, {%0,%1};"
                 : "+r"(c[0]), "+r"(c[1])
                 : "r"(a[0]), "r"(a[1]), "r"(a[2]), "r"(a[3]), "r"(b[0]), "r"(b[1]));
}
__device__ __forceinline__ uint32_t hfma2_(uint32_t a, uint32_t b, uint32_t c) {
    uint32_t d;
    asm("fma.rn.f16x2 %0, %1, %2, %3;" : "=r"(d) : "r"(a), "r"(b), "r"(c));
    return d;
}
__device__ __forceinline__ uint32_t hadd2_(uint32_t a, uint32_t b) {
    uint32_t d;
    asm("add.rn.f16x2 %0, %1, %2;" : "=r"(d) : "r"(a), "r"(b));
    return d;
}

// ---------------- preprocessing ----------------
__global__ void prep_kernel(const float* __restrict__ enc, const float* __restrict__ cb) {
    int idx = blockIdx.x * blockDim.x + threadIdx.x;
    const int n4e = N_Q * DIMS / 4;
    const float4* src;
    __half2* ph;
    int j;
    if (idx < n4e) { src = (const float4*)enc; j = idx; ph = (__half2*)g_enc_h; }
    else           { src = (const float4*)cb;  j = idx - n4e; ph = (__half2*)g_cb_h; }
    float4 v = src[j];
    ph[j * 2]     = __floats2half2_rn(v.x, v.y);
    ph[j * 2 + 1] = __floats2half2_rn(v.z, v.w);
}

__global__ void csq_kernel(const float* __restrict__ cb) {
    int row  = blockIdx.x * 8 + (threadIdx.x >> 5);
    int lane = threadIdx.x & 31;
    float v0 = cb[row * DIMS + lane];
    float v1 = cb[row * DIMS + 32 + lane];
    float s  = v0 * v0 + v1 * v1;
    #pragma unroll
    for (int off = 16; off; off >>= 1) s += __shfl_xor_sync(0xffffffffu, s, off);
    if (lane == 0) g_csq[row] = s;
}

// ---------------- B tile loader ----------------
__device__ __forceinline__ void load_B_tile(uint32_t smem_base, int tile, int stage, int tid) {
    const int kb = tile * NT;
    for (int c = tid; c < 1024; c += THREADS) {
        int r = c >> 3;
        int q = c & 7;
        const char* src = (const char*)g_cb_h + (size_t)(kb + r) * 128 + q * 16;
        uint32_t dst = smem_base + SM_B + stage * STAGE + r * ROWB + q * 16;
        CP16(dst, src);
    }
    if (tid < 32) {
        uint32_t dst = smem_base + SM_B + stage * STAGE + TERM_BYTES + tid * 16;
        CP16(dst, (const char*)g_csq + (size_t)kb * 4 + tid * 16);
    }
}

// ---------------- main kernel ----------------
__global__ __launch_bounds__(THREADS, 1)
void vq_main(const float* __restrict__ enc, const float* __restrict__ cb,
             float* __restrict__ out)
{
    extern __shared__ char smem[];
    const uint32_t smem_base = smem_u32(smem);
    const int tid  = threadIdx.x;
    const int wid  = tid >> 5;
    const int lane = tid & 31;
    const int m0   = blockIdx.x * MT;
    const bool is_mma = (wid < 16);
    const int wm = wid & 3;               // MMA: 4 warps over M (32 rows each)
    const int wn = wid >> 2;              // MMA: 4 warps over 24-col strips

    // ---- start B pipeline (stages 0..2) ----
    load_B_tile(smem_base, 0, 0, tid); CP_COMMIT();
    load_B_tile(smem_base, 1, 1, tid); CP_COMMIT();
    load_B_tile(smem_base, 2, 2, tid); CP_COMMIT();

    // ---- stage A (f16), padded rows ----
    for (int c = tid; c < 1024; c += THREADS) {
        int r = c >> 3;
        int q = c & 7;
        const uint4* src = (const uint4*)(g_enc_h + (size_t)(m0 + r) * DIMS) + q;
        *(uint4*)(smem + SM_A + r * ROWB + q * 16) = *src;
    }
    __syncthreads();

    // =========== per-role persistent state ===========
    // MMA warps
    uint32_t af[4][2][4];                 // A fragments [ks][i][frag]
    uint32_t b_x4_base = 0, b_x2_base = 0;
    // scalar warps
    uint32_t ar[32];                      // query row as 32 half2
    int sq = 0;

    if (is_mma) {
        const uint32_t a_base = smem_base + SM_A
            + (wm * 32 + (lane & 15)) * ROWB + ((lane >> 4) & 1) * 16;
        #pragma unroll
        for (int ks = 0; ks < 4; ++ks)
            #pragma unroll
            for (int i = 0; i < 2; ++i)
                ldsm_x4(af[ks][i], a_base + i * 16 * ROWB + ks * 32);
        b_x4_base = smem_base + SM_B
            + (wn * 24 + (lane >> 4) * 8 + (lane & 7)) * ROWB + ((lane >> 3) & 1) * 16;
        const int l4 = lane & 15;
        b_x2_base = smem_base + SM_B
            + (wn * 24 + 16 + (l4 & 7)) * ROWB + (l4 >> 3) * 16;
    } else {
        sq = (wid - 16) * 32 + lane;      // owned query row
        const uint32_t arow = smem_base + SM_A + sq * ROWB;
        #pragma unroll
        for (int u = 0; u < 8; ++u) {
            uint4 v;
            asm volatile("ld.shared.v4.u32 {%0,%1,%2,%3}, [%4];"
                         : "=r"(v.x), "=r"(v.y), "=r"(v.z), "=r"(v.w)
                         : "r"(arow + u * 16));
            ar[u * 4 + 0] = v.x; ar[u * 4 + 1] = v.y;
            ar[u * 4 + 2] = v.z; ar[u * 4 + 3] = v.w;
        }
    }

    // top-K state: MMA rows use [0..3] with top-3; scalar uses row 0 slots as top-4
    float bm1[4], bm2[4], bm3[4], sm4;
    int   bi1[4], bi2[4], bi3[4], si4;
    #pragma unroll
    for (int r = 0; r < 4; ++r) {
        bm1[r] = 3.4e38f; bm2[r] = 3.4e38f; bm3[r] = 3.4e38f;
        bi1[r] = 0; bi2[r] = 0; bi3[r] = 0;
    }
    sm4 = 3.4e38f; si4 = 0;

    uint32_t acc[2][3][2];                // MMA f16x2 accumulators

    for (int t = 0; t < NTILES; ++t) {
        const int stage = t & 3;
        CP_WAIT2();
        __syncthreads();
        if (t + 3 < NTILES) load_B_tile(smem_base, t + 3, (t + 3) & 3, tid);
        CP_COMMIT();

        const int kb = t * NT;
        const uint32_t stb = stage * STAGE;

        if (is_mma) {
            #pragma unroll
            for (int i = 0; i < 2; ++i)
                #pragma unroll
                for (int j = 0; j < 3; ++j) { acc[i][j][0] = 0u; acc[i][j][1] = 0u; }

            #pragma unroll
            for (int ks = 0; ks < 4; ++ks) {
                uint32_t bh[3][2];
                {
                    uint32_t r4[4], r2[2];
                    ldsm_x4(r4, b_x4_base + stb + ks * 32);
                    ldsm_x2(r2, b_x2_base + stb + ks * 32);
                    bh[0][0] = r4[0]; bh[0][1] = r4[1];
                    bh[1][0] = r4[2]; bh[1][1] = r4[3];
                    bh[2][0] = r2[0]; bh[2][1] = r2[1];
                }
                #pragma unroll
                for (int i = 0; i < 2; ++i)
                    #pragma unroll
                    for (int j = 0; j < 3; ++j) mma16816_h(acc[i][j], af[ks][i], bh[j]);
            }

            // fused argmin epilogue (top-3 per owned query row)
            #pragma unroll
            for (int j = 0; j < 3; ++j) {
                float2 cs = *(const float2*)(smem + SM_B + stb + TERM_BYTES
                            + (wn * 24 + j * 8 + (lane & 3) * 2) * 4);
                const int k0 = kb + wn * 24 + j * 8 + (lane & 3) * 2;
                #pragma unroll
                for (int i = 0; i < 2; ++i) {
                    #pragma unroll
                    for (int h = 0; h < 2; ++h) {
                        const int ri = i * 2 + h;
                        float2 dv = __half22float2(*(const __half2*)&acc[i][j][h]);
                        #pragma unroll
                        for (int c = 0; c < 2; ++c) {
                            float m = fmaf(-2.f, c ? dv.y : dv.x, c ? cs.y : cs.x);
                            const int k = k0 + c;
                            if (m < bm3[ri]) {
                                if (m < bm1[ri]) {
                                    bm3[ri] = bm2[ri]; bi3[ri] = bi2[ri];
                                    bm2[ri] = bm1[ri]; bi2[ri] = bi1[ri];
                                    bm1[ri] = m;       bi1[ri] = k;
                                } else if (m < bm2[ri]) {
                                    bm3[ri] = bm2[ri]; bi3[ri] = bi2[ri];
                                    bm2[ri] = m;       bi2[ri] = k;
                                } else {
                                    bm3[ri] = m;       bi3[ri] = k;
                                }
                            }
                        }
                    }
                }
            }
        } else {
            // scalar warps: cols 96..127, 1 query/lane, HFMA2 dot products
            const uint32_t bbase = smem_base + SM_B + stb + 96 * ROWB;
            const uint32_t csbase = smem_base + SM_B + stb + TERM_BYTES + 96 * 4;
            #pragma unroll 4
            for (int c = 0; c < 32; ++c) {
                const uint32_t rb = bbase + c * ROWB;
                uint32_t a0 = 0, a1 = 0, a2 = 0, a3 = 0;
                #pragma unroll
                for (int u = 0; u < 8; ++u) {
                    uint4 v;
                    asm volatile("ld.shared.v4.u32 {%0,%1,%2,%3}, [%4];"
                                 : "=r"(v.x), "=r"(v.y), "=r"(v.z), "=r"(v.w)
                                 : "r"(rb + u * 16));
                    a0 = hfma2_(ar[u * 4 + 0], v.x, a0);
                    a1 = hfma2_(ar[u * 4 + 1], v.y, a1);
                    a2 = hfma2_(ar[u * 4 + 2], v.z, a2);
                    a3 = hfma2_(ar[u * 4 + 3], v.w, a3);
                }
                uint32_t s = hadd2_(hadd2_(a0, a1), hadd2_(a2, a3));
                float2 f = __half22float2(*(const __half2*)&s);
                float dot = f.x + f.y;
                float cs;
                asm volatile("ld.shared.f32 %0, [%1];" : "=f"(cs) : "r"(csbase + c * 4));
                float m = fmaf(-2.f, dot, cs);
                const int k = kb + 96 + c;
                if (m < sm4) {
                    if (m < bm2[0]) {
                        if (m < bm1[0]) {
                            sm4 = bm3[0]; si4 = bi3[0];
                            bm3[0] = bm2[0]; bi3[0] = bi2[0];
                            bm2[0] = bm1[0]; bi2[0] = bi1[0];
                            bm1[0] = m; bi1[0] = k;
                        } else {
                            sm4 = bm3[0]; si4 = bi3[0];
                            bm3[0] = bm2[0]; bi3[0] = bi2[0];
                            bm2[0] = m; bi2[0] = k;
                        }
                    } else {
                        if (m < bm3[0]) {
                            sm4 = bm3[0]; si4 = bi3[0];
                            bm3[0] = m; bi3[0] = k;
                        } else {
                            sm4 = m; si4 = k;
                        }
                    }
                }
            }
        }
    }

    // ---- candidate dump: per query 52 slots (48 MMA + 4 scalar) ----
    __syncthreads();
    {
        float2* cand = (float2*)(smem + SM_CAND);
        if (is_mma) {
            const int slot = wn * 4 + (lane & 3);        // 0..15
            #pragma unroll
            for (int i = 0; i < 2; ++i)
                #pragma unroll
                for (int h = 0; h < 2; ++h) {
                    const int ri = i * 2 + h;
                    const int q  = wm * 32 + i * 16 + h * 8 + (lane >> 2);
                    float2* p = &cand[q * 52 + slot * 3];
                    p[0] = make_float2(bm1[ri], __int_as_float(bi1[ri]));
                    p[1] = make_float2(bm2[ri], __int_as_float(bi2[ri]));
                    p[2] = make_float2(bm3[ri], __int_as_float(bi3[ri]));
                }
        } else {
            float2* p = &cand[sq * 52 + 48];
            p[0] = make_float2(bm1[0], __int_as_float(bi1[0]));
            p[1] = make_float2(bm2[0], __int_as_float(bi2[0]));
            p[2] = make_float2(bm3[0], __int_as_float(bi3[0]));
            p[3] = make_float2(sm4,    __int_as_float(si4));
        }
    }
    __syncthreads();

    // ---- margin-gated exact fp32 rescore (warps 0-15, 8 queries each) ----
    if (is_mma) {
        const float2* cand = (const float2*)(smem + SM_CAND);
        int* bestk = (int*)(smem + SM_BESTK);
        for (int it = 0; it < 8; ++it) {
            const int q = wid * 8 + it;
            float2 c0 = cand[q * 52 + lane];
            float2 c1 = (lane < 20) ? cand[q * 52 + 32 + lane]
                                    : make_float2(3.4e38f, __int_as_float(0));
            float lm = fminf(c0.x, c1.x);
            #pragma unroll
            for (int off = 16; off; off >>= 1)
                lm = fminf(lm, __shfl_xor_sync(0xffffffffu, lm, off));
            const float thresh = lm + TAU;

            const float4* er = (const float4*)(enc + (size_t)(m0 + q) * DIMS);
            float bm = 3.4e38f; int bk = 0x7fffffff;
            #pragma unroll
            for (int rnd = 0; rnd < 2; ++rnd) {
                float2 cc = rnd ? c1 : c0;
                if (cc.x <= thresh) {
                    const int k = __float_as_int(cc.y);
                    const float4* cr = (const float4*)(cb + (size_t)k * DIMS);
                    float s = 0.f;
                    #pragma unroll
                    for (int u = 0; u < 16; ++u) {
                        float4 a = er[u], b = cr[u];
                        s = fmaf(a.x, b.x, s); s = fmaf(a.y, b.y, s);
                        s = fmaf(a.z, b.z, s); s = fmaf(a.w, b.w, s);
                    }
                    float m = fmaf(-2.f, s, g_csq[k]);
                    if (m < bm || (m == bm && k < bk)) { bm = m; bk = k; }
                }
            }
            #pragma unroll
            for (int off = 16; off; off >>= 1) {
                float om = __shfl_xor_sync(0xffffffffu, bm, off);
                int   ok = __shfl_xor_sync(0xffffffffu, bk, off);
                if (om < bm || (om == bm && ok < bk)) { bm = om; bk = ok; }
            }
            if (lane == 0) bestk[q] = bk;
        }
    }
    __syncthreads();

    // ---- gather output rows ----
    {
        const int* bestk = (const int*)(smem + SM_BESTK);
        const float4* cb4 = (const float4*)cb;
        float4* out4 = (float4*)out;
        for (int lin = tid; lin < 2048; lin += THREADS) {
            int q = lin >> 4;
            int quad = lin & 15;
            out4[(size_t)(m0 + q) * 16 + quad] = cb4[(size_t)bestk[q] * 16 + quad];
        }
    }
}

extern "C" void kernel_launch(void* const* d_in, const int* in_sizes, int n_in,
                              void* d_out, int out_size) {
    const float* enc = (const float*)d_in[0];
    const float* cb  = (const float*)d_in[1];
    if (n_in >= 2 && in_sizes[0] == K_CB * DIMS && in_sizes[1] == N_Q * DIMS) {
        enc = (const float*)d_in[1];
        cb  = (const float*)d_in[0];
    }
    float* out = (float*)d_out;

    cudaFuncSetAttribute(vq_main, cudaFuncAttributeMaxDynamicSharedMemorySize, SMEM_TOTAL);

    prep_kernel<<<(N_Q * DIMS + K_CB * DIMS) / 4 / 256, 256>>>(enc, cb);
    csq_kernel<<<K_CB / 8, 256>>>(cb);
    vq_main<<<N_Q / MT, THREADS, SMEM_TOTAL>>>(enc, cb, out);
}

// round 13
// speedup vs baseline: 2.3794x; 2.3794x over previous
#include <cuda_runtime.h>
#include <cuda_fp8.h>
#include <cstdint>

#define N_Q   16384
#define DIMS  64
#define K_CB  8192
#define MT    128            // queries per CTA
#define NT    128            // codewords per tile
#define NTILES (K_CB / NT)   // 64
#define THREADS 512

#define TAU 6.0f

// padded fp8 row: 64 data + 16 pad = 80 bytes (conflict-free ldmatrix, stride 80)
#define ROWB 80
#define TERM_BYTES (128 * ROWB)      // 10240 per tile
#define STAGE (TERM_BYTES + 512)     // tile + csq = 10752

// shared memory layout (bytes)
#define SM_B     0                       // 4 stages x 10752 = 43008
#define SM_A     43008                   // 10240
#define SM_CAND  53248                   // 128 q x 64 slots x 8B = 65536
#define SM_BESTK 118784                  // 128 ints
#define SMEM_TOTAL 119296

__device__ __align__(16) uint8_t g_enc_f8[N_Q * DIMS];
__device__ __align__(16) uint8_t g_cb_f8[K_CB * DIMS];
__device__ __align__(16) float   g_csq[K_CB];

// ---------------- helpers ----------------
__device__ __forceinline__ uint32_t smem_u32(const void* p) {
    uint32_t a;
    asm("{ .reg .u64 t; cvta.to.shared.u64 t, %1; cvt.u32.u64 %0, t; }" : "=r"(a) : "l"(p));
    return a;
}
#define CP16(d, s)  asm volatile("cp.async.cg.shared.global [%0], [%1], 16;" :: "r"(d), "l"(s))
#define CP_COMMIT() asm volatile("cp.async.commit_group;" ::: "memory")
#define CP_WAIT2()  asm volatile("cp.async.wait_group 2;" ::: "memory")

__device__ __forceinline__ void ldsm_x4(uint32_t* r, uint32_t addr) {
    asm volatile("ldmatrix.sync.aligned.m8n8.x4.shared.b16 {%0,%1,%2,%3}, [%4];"
                 : "=r"(r[0]), "=r"(r[1]), "=r"(r[2]), "=r"(r[3]) : "r"(addr));
}
__device__ __forceinline__ void fmma8(float* c, const uint32_t* a, const uint32_t* b) {
    asm volatile("mma.sync.aligned.m16n8k32.row.col.f32.e4m3.e4m3.f32 "
                 "{%0,%1,%2,%3}, {%4,%5,%6,%7}, {%8,%9}, {%0,%1,%2,%3};"
                 : "+f"(c[0]), "+f"(c[1]), "+f"(c[2]), "+f"(c[3])
                 : "r"(a[0]), "r"(a[1]), "r"(a[2]), "r"(a[3]), "r"(b[0]), "r"(b[1]));
}

// ---------------- preprocessing: fp32 -> e4m3 ----------------
__global__ void prep_kernel(const float* __restrict__ enc, const float* __restrict__ cb) {
    int idx = blockIdx.x * blockDim.x + threadIdx.x;     // one float4 -> 4 bytes
    const int n4e = N_Q * DIMS / 4;
    const float4* src;
    uchar4* dst;
    int j;
    if (idx < n4e) { src = (const float4*)enc; j = idx; dst = (uchar4*)g_enc_f8; }
    else           { src = (const float4*)cb;  j = idx - n4e; dst = (uchar4*)g_cb_f8; }
    float4 v = src[j];
    uchar4 o;
    o.x = (uint8_t)__nv_cvt_float_to_fp8(v.x, __NV_SATFINITE, __NV_E4M3);
    o.y = (uint8_t)__nv_cvt_float_to_fp8(v.y, __NV_SATFINITE, __NV_E4M3);
    o.z = (uint8_t)__nv_cvt_float_to_fp8(v.z, __NV_SATFINITE, __NV_E4M3);
    o.w = (uint8_t)__nv_cvt_float_to_fp8(v.w, __NV_SATFINITE, __NV_E4M3);
    dst[j] = o;
}

__global__ void csq_kernel(const float* __restrict__ cb) {
    int row  = blockIdx.x * 8 + (threadIdx.x >> 5);
    int lane = threadIdx.x & 31;
    float v0 = cb[row * DIMS + lane];
    float v1 = cb[row * DIMS + 32 + lane];
    float s  = v0 * v0 + v1 * v1;
    #pragma unroll
    for (int off = 16; off; off >>= 1) s += __shfl_xor_sync(0xffffffffu, s, off);
    if (lane == 0) g_csq[row] = s;
}

// ---------------- B tile loader: 128 rows x 64B = 512 x 16B chunks ----------------
__device__ __forceinline__ void load_B_tile(uint32_t smem_base, int tile, int stage, int tid) {
    const int kb = tile * NT;
    {
        int r = tid >> 2;                 // codeword row within tile
        int q = tid & 3;                  // 16B chunk
        const char* src = (const char*)g_cb_f8 + (size_t)(kb + r) * 64 + q * 16;
        uint32_t dst = smem_base + SM_B + stage * STAGE + r * ROWB + q * 16;
        CP16(dst, src);
    }
    if (tid < 32) {
        uint32_t dst = smem_base + SM_B + stage * STAGE + TERM_BYTES + tid * 16;
        CP16(dst, (const char*)g_csq + (size_t)kb * 4 + tid * 16);
    }
}

// ---------------- main kernel ----------------
__global__ __launch_bounds__(THREADS, 1)
void vq_main(const float* __restrict__ enc, const float* __restrict__ cb,
             float* __restrict__ out)
{
    extern __shared__ char smem[];
    const uint32_t smem_base = smem_u32(smem);
    const int tid  = threadIdx.x;
    const int wid  = tid >> 5;
    const int lane = tid & 31;
    const int wm   = wid & 3;             // 4 warps over M (32 rows each)
    const int wn   = wid >> 2;            // 4 warps over N (32 cols each)
    const int m0   = blockIdx.x * MT;

    // ---- start B pipeline immediately (stages 0..2) ----
    load_B_tile(smem_base, 0, 0, tid); CP_COMMIT();
    load_B_tile(smem_base, 1, 1, tid); CP_COMMIT();
    load_B_tile(smem_base, 2, 2, tid); CP_COMMIT();

    // ---- stage A (fp8), padded rows: 512 x 16B chunks ----
    {
        int r = tid >> 2;
        int q = tid & 3;
        const uint4* src = (const uint4*)(g_enc_f8 + (size_t)(m0 + r) * 64) + q;
        *(uint4*)(smem + SM_A + r * ROWB + q * 16) = *src;
    }
    __syncthreads();

    // ldmatrix base addresses (16 rows x 32B coverage per x4)
    const uint32_t a_base = smem_base + SM_A
        + (wm * 32 + (lane & 15)) * ROWB + (lane >> 4) * 16;
    const uint32_t b_base0 = smem_base + SM_B
        + (wn * 32 + (lane & 15)) * ROWB + (lane >> 4) * 16;

    // ---- hoist A fragments (tile-invariant): [ks][m-tile][frag] ----
    uint32_t af[2][2][4];
    #pragma unroll
    for (int ks = 0; ks < 2; ++ks)
        #pragma unroll
        for (int i = 0; i < 2; ++i)
            ldsm_x4(af[ks][i], a_base + i * 16 * ROWB + ks * 32);

    // top-4 per owned query row (4 rows/thread), slice = 512 codewords
    float bm1[4], bm2[4], bm3[4], bm4[4];
    int   bi1[4], bi2[4], bi3[4], bi4[4];
    #pragma unroll
    for (int r = 0; r < 4; ++r) {
        bm1[r] = 3.4e38f; bm2[r] = 3.4e38f; bm3[r] = 3.4e38f; bm4[r] = 3.4e38f;
        bi1[r] = 0; bi2[r] = 0; bi3[r] = 0; bi4[r] = 0;
    }

    float acc[2][4][4];

    for (int t = 0; t < NTILES; ++t) {
        const int stage = t & 3;
        CP_WAIT2();                       // tile t resident
        __syncthreads();                  // stage (t+3)&3 fully consumed by all warps
        if (t + 3 < NTILES) load_B_tile(smem_base, t + 3, (t + 3) & 3, tid);
        CP_COMMIT();

        #pragma unroll
        for (int i = 0; i < 2; ++i)
            #pragma unroll
            for (int j = 0; j < 4; ++j)
                #pragma unroll
                for (int r = 0; r < 4; ++r) acc[i][j][r] = 0.f;

        const uint32_t bs = b_base0 + stage * STAGE;
        #pragma unroll
        for (int ks = 0; ks < 2; ++ks) {
            // B fragments: 2 x ldsm.x4 cover n0-31 for this k32 chunk
            uint32_t bf[4][2];
            #pragma unroll
            for (int nt = 0; nt < 2; ++nt) {
                uint32_t r4[4];
                ldsm_x4(r4, bs + nt * 16 * ROWB + ks * 32);
                bf[nt * 2 + 0][0] = r4[0]; bf[nt * 2 + 0][1] = r4[2];
                bf[nt * 2 + 1][0] = r4[1]; bf[nt * 2 + 1][1] = r4[3];
            }
            #pragma unroll
            for (int i = 0; i < 2; ++i)
                #pragma unroll
                for (int j = 0; j < 4; ++j) fmma8(acc[i][j], af[ks][i], bf[j]);
        }

        // ---- fused argmin epilogue (top-4 per owned query row) ----
        const int kb = t * NT;
        #pragma unroll
        for (int j = 0; j < 4; ++j) {
            float2 cs = *(const float2*)(smem + SM_B + stage * STAGE + TERM_BYTES
                        + (wn * 32 + j * 8 + (lane & 3) * 2) * 4);
            const int k0 = kb + wn * 32 + j * 8 + (lane & 3) * 2;
            #pragma unroll
            for (int i = 0; i < 2; ++i) {
                #pragma unroll
                for (int h = 0; h < 2; ++h) {
                    const int ri = i * 2 + h;
                    #pragma unroll
                    for (int c = 0; c < 2; ++c) {
                        float m = fmaf(-2.0f, acc[i][j][h * 2 + c], c ? cs.y : cs.x);
                        const int k = k0 + c;
                        if (m < bm4[ri]) {
                            if (m < bm2[ri]) {
                                if (m < bm1[ri]) {
                                    bm4[ri]=bm3[ri]; bi4[ri]=bi3[ri];
                                    bm3[ri]=bm2[ri]; bi3[ri]=bi2[ri];
                                    bm2[ri]=bm1[ri]; bi2[ri]=bi1[ri];
                                    bm1[ri]=m;       bi1[ri]=k;
                                } else {
                                    bm4[ri]=bm3[ri]; bi4[ri]=bi3[ri];
                                    bm3[ri]=bm2[ri]; bi3[ri]=bi2[ri];
                                    bm2[ri]=m;       bi2[ri]=k;
                                }
                            } else {
                                if (m < bm3[ri]) {
                                    bm4[ri]=bm3[ri]; bi4[ri]=bi3[ri];
                                    bm3[ri]=m;       bi3[ri]=k;
                                } else {
                                    bm4[ri]=m;       bi4[ri]=k;
                                }
                            }
                        }
                    }
                }
            }
        }
        // next iteration's leading sync protects stage reuse
    }

    // ---- candidate dump: 16 slices x 4 (m, k) per query ----
    __syncthreads();
    {
        float2* cand = (float2*)(smem + SM_CAND);
        const int slot = wn * 4 + (lane & 3);            // 0..15
        #pragma unroll
        for (int i = 0; i < 2; ++i)
            #pragma unroll
            for (int h = 0; h < 2; ++h) {
                const int ri = i * 2 + h;
                const int q  = wm * 32 + i * 16 + h * 8 + (lane >> 2);
                float2* p = &cand[q * 64 + slot * 4];
                p[0] = make_float2(bm1[ri], __int_as_float(bi1[ri]));
                p[1] = make_float2(bm2[ri], __int_as_float(bi2[ri]));
                p[2] = make_float2(bm3[ri], __int_as_float(bi3[ri]));
                p[3] = make_float2(bm4[ri], __int_as_float(bi4[ri]));
            }
    }
    __syncthreads();

    // ---- margin-gated exact fp32 rescore: one warp per query ----
    {
        const float2* cand = (const float2*)(smem + SM_CAND);
        int* bestk = (int*)(smem + SM_BESTK);
        for (int it = 0; it < 8; ++it) {
            const int q = wid * 8 + it;
            float2 c0 = cand[q * 64 + lane];
            float2 c1 = cand[q * 64 + 32 + lane];
            float lm = fminf(c0.x, c1.x);
            #pragma unroll
            for (int off = 16; off; off >>= 1)
                lm = fminf(lm, __shfl_xor_sync(0xffffffffu, lm, off));
            const float thresh = lm + TAU;

            const float4* er = (const float4*)(enc + (size_t)(m0 + q) * DIMS);
            float bm = 3.4e38f; int bk = 0x7fffffff;
            #pragma unroll
            for (int rnd = 0; rnd < 2; ++rnd) {
                float2 cc = rnd ? c1 : c0;
                if (cc.x <= thresh) {
                    const int k = __float_as_int(cc.y);
                    const float4* cr = (const float4*)(cb + (size_t)k * DIMS);
                    float s = 0.f;
                    #pragma unroll
                    for (int u = 0; u < 16; ++u) {
                        float4 a = er[u], b = cr[u];
                        s = fmaf(a.x, b.x, s); s = fmaf(a.y, b.y, s);
                        s = fmaf(a.z, b.z, s); s = fmaf(a.w, b.w, s);
                    }
                    float m = fmaf(-2.f, s, g_csq[k]);
                    if (m < bm || (m == bm && k < bk)) { bm = m; bk = k; }
                }
            }
            #pragma unroll
            for (int off = 16; off; off >>= 1) {
                float om = __shfl_xor_sync(0xffffffffu, bm, off);
                int   ok = __shfl_xor_sync(0xffffffffu, bk, off);
                if (om < bm || (om == bm && ok < bk)) { bm = om; bk = ok; }
            }
            if (lane == 0) bestk[q] = bk;
        }
    }
    __syncthreads();

    // ---- gather output rows ----
    {
        const int* bestk = (const int*)(smem + SM_BESTK);
        const float4* cb4 = (const float4*)cb;
        float4* out4 = (float4*)out;
        #pragma unroll
        for (int i = 0; i < 4; ++i) {
            int lin = tid + i * THREADS;            // 0..2047
            int q = lin >> 4;
            int quad = lin & 15;
            out4[(size_t)(m0 + q) * 16 + quad] = cb4[(size_t)bestk[q] * 16 + quad];
        }
    }
}

extern "C" void kernel_launch(void* const* d_in, const int* in_sizes, int n_in,
                              void* d_out, int out_size) {
    const float* enc = (const float*)d_in[0];
    const float* cb  = (const float*)d_in[1];
    if (n_in >= 2 && in_sizes[0] == K_CB * DIMS && in_sizes[1] == N_Q * DIMS) {
        enc = (const float*)d_in[1];
        cb  = (const float*)d_in[0];
    }
    float* out = (float*)d_out;

    cudaFuncSetAttribute(vq_main, cudaFuncAttributeMaxDynamicSharedMemorySize, SMEM_TOTAL);

    prep_kernel<<<(N_Q * DIMS + K_CB * DIMS) / 4 / 256, 256>>>(enc, cb);
    csq_kernel<<<K_CB / 8, 256>>>(cb);
    vq_main<<<N_Q / MT, THREADS, SMEM_TOTAL>>>(enc, cb, out);
}

// round 14
// speedup vs baseline: 2.4542x; 1.0314x over previous
#include <cuda_runtime.h>
#include <cuda_bf16.h>
#include <cstdint>

#define N_Q   16384
#define DIMS  64
#define K_CB  8192
#define MT    128            // queries per tile-row block
#define NT    128            // codewords per k-tile
#define NQTILES (N_Q / MT)   // 128
#define NKTILES (K_CB / NT)  // 64
#define N_ITEMS (NQTILES * 8)   // 1024 items of 8 k-tiles
#define NCTAS 148
#define THREADS 512
#define TAU 2.5f

// padded bf16 row: 64 elems + 8 pad = 72 elems = 144 bytes
#define ROWB 144
#define TERM_BYTES (128 * ROWB)      // 18432 per tile (128 rows)
#define STAGE (TERM_BYTES + 512)     // tile + csq = 18944

// shared memory layout (bytes)
#define SM_B     0                       // 4 stages x 18944 = 75776
#define SM_A     75776                   // 18432
#define SM_CAND  94208                   // 128 q x 48 slots x 8B = 49152
#define SMEM_TOTAL 143872

__device__ __nv_bfloat16 g_enc_bf[N_Q * DIMS];
__device__ __nv_bfloat16 g_cb_bf[K_CB * DIMS];
__device__ __align__(16) float g_csq[K_CB];
__device__ unsigned long long g_best[N_Q];

// ---------------- helpers ----------------
__device__ __forceinline__ uint32_t smem_u32(const void* p) {
    uint32_t a;
    asm("{ .reg .u64 t; cvta.to.shared.u64 t, %1; cvt.u32.u64 %0, t; }" : "=r"(a) : "l"(p));
    return a;
}
#define CP16(d, s)  asm volatile("cp.async.cg.shared.global [%0], [%1], 16;" :: "r"(d), "l"(s))
#define CP_COMMIT() asm volatile("cp.async.commit_group;" ::: "memory")
#define CP_WAIT2()  asm volatile("cp.async.wait_group 2;" ::: "memory")

__device__ __forceinline__ void ldsm_x4(uint32_t* r, uint32_t addr) {
    asm volatile("ldmatrix.sync.aligned.m8n8.x4.shared.b16 {%0,%1,%2,%3}, [%4];"
                 : "=r"(r[0]), "=r"(r[1]), "=r"(r[2]), "=r"(r[3]) : "r"(addr));
}
__device__ __forceinline__ void mma16816(float* c, const uint32_t* a, const uint32_t* b) {
    asm volatile("mma.sync.aligned.m16n8k16.row.col.f32.bf16.bf16.f32 "
                 "{%0,%1,%2,%3}, {%4,%5,%6,%7}, {%8,%9}, {%0,%1,%2,%3};"
                 : "+f"(c[0]), "+f"(c[1]), "+f"(c[2]), "+f"(c[3])
                 : "r"(a[0]), "r"(a[1]), "r"(a[2]), "r"(a[3]), "r"(b[0]), "r"(b[1]));
}

// ---------------- preprocessing ----------------
__global__ void prep_kernel(const float* __restrict__ enc, const float* __restrict__ cb) {
    int idx = blockIdx.x * blockDim.x + threadIdx.x;     // one float4
    if (idx < N_Q) g_best[idx] = 0xFFFFFFFFFFFFFFFFULL;
    const int n4e = N_Q * DIMS / 4;
    const float4* src;
    __nv_bfloat162* ph;
    int j;
    if (idx < n4e) { src = (const float4*)enc; j = idx; ph = (__nv_bfloat162*)g_enc_bf; }
    else           { src = (const float4*)cb;  j = idx - n4e; ph = (__nv_bfloat162*)g_cb_bf; }
    float4 v = src[j];
    __nv_bfloat162 a; a.x = __float2bfloat16(v.x); a.y = __float2bfloat16(v.y);
    __nv_bfloat162 b; b.x = __float2bfloat16(v.z); b.y = __float2bfloat16(v.w);
    ph[j * 2] = a; ph[j * 2 + 1] = b;
}

__global__ void csq_kernel(const float* __restrict__ cb) {
    int row  = blockIdx.x * 8 + (threadIdx.x >> 5);
    int lane = threadIdx.x & 31;
    float v0 = cb[row * DIMS + lane];
    float v1 = cb[row * DIMS + 32 + lane];
    float s  = v0 * v0 + v1 * v1;
    #pragma unroll
    for (int off = 16; off; off >>= 1) s += __shfl_xor_sync(0xffffffffu, s, off);
    if (lane == 0) g_csq[row] = s;
}

// ---------------- B tile loader (depends only on k-tile) ----------------
__device__ __forceinline__ void load_B_tile(uint32_t smem_base, int ktile, int stage, int tid) {
    const int kb = ktile * NT;
    #pragma unroll
    for (int i = 0; i < 2; ++i) {
        int c = tid + i * THREADS;        // 0..1023
        int r = c >> 3;                   // codeword row within tile
        int q = c & 7;                    // 16B chunk
        const char* src = (const char*)g_cb_bf + (size_t)(kb + r) * 128 + q * 16;
        uint32_t dst = smem_base + SM_B + stage * STAGE + r * ROWB + q * 16;
        CP16(dst, src);
    }
    if (tid < 32) {
        uint32_t dst = smem_base + SM_B + stage * STAGE + TERM_BYTES + tid * 16;
        CP16(dst, (const char*)g_csq + (size_t)kb * 4 + tid * 16);
    }
}

// ---------------- flush: dump top-3, gated exact rescore, atomic merge ----------------
__device__ __forceinline__ void flush_cands(
    char* smem, const float* enc, const float* cb, int m0r,
    int wid, int lane, int wm, int wn,
    float* bm1, float* bm2, float* bm3, int* bi1, int* bi2, int* bi3)
{
    __syncthreads();
    float2* cand = (float2*)(smem + SM_CAND);
    const int slot = wn * 4 + (lane & 3);            // 0..15
    #pragma unroll
    for (int i = 0; i < 2; ++i)
        #pragma unroll
        for (int h = 0; h < 2; ++h) {
            const int ri = i * 2 + h;
            const int q  = wm * 32 + i * 16 + h * 8 + (lane >> 2);
            float2* p = &cand[q * 48 + slot * 3];
            p[0] = make_float2(bm1[ri], __int_as_float(bi1[ri]));
            p[1] = make_float2(bm2[ri], __int_as_float(bi2[ri]));
            p[2] = make_float2(bm3[ri], __int_as_float(bi3[ri]));
        }
    __syncthreads();

    for (int it = 0; it < 8; ++it) {
        const int q = wid * 8 + it;
        float2 c0 = cand[q * 48 + lane];
        float2 c1 = (lane < 16) ? cand[q * 48 + 32 + lane]
                                : make_float2(3.4e38f, __int_as_float(0));
        float lm = fminf(c0.x, c1.x);
        #pragma unroll
        for (int off = 16; off; off >>= 1)
            lm = fminf(lm, __shfl_xor_sync(0xffffffffu, lm, off));
        const float thresh = lm + TAU;

        const float4* er = (const float4*)(enc + (size_t)(m0r + q) * DIMS);
        float bm = 3.4e38f; int bk = 0x7fffffff;
        #pragma unroll
        for (int rnd = 0; rnd < 2; ++rnd) {
            float2 cc = rnd ? c1 : c0;
            if (cc.x <= thresh) {
                const int k = __float_as_int(cc.y);
                const float4* cr = (const float4*)(cb + (size_t)k * DIMS);
                float s = 0.f;
                #pragma unroll
                for (int u = 0; u < 16; ++u) {
                    float4 a = er[u], b = cr[u];
                    s = fmaf(a.x, b.x, s); s = fmaf(a.y, b.y, s);
                    s = fmaf(a.z, b.z, s); s = fmaf(a.w, b.w, s);
                }
                float m = fmaf(-2.f, s, g_csq[k]);
                if (m < bm || (m == bm && k < bk)) { bm = m; bk = k; }
            }
        }
        #pragma unroll
        for (int off = 16; off; off >>= 1) {
            float om = __shfl_xor_sync(0xffffffffu, bm, off);
            int   ok = __shfl_xor_sync(0xffffffffu, bk, off);
            if (om < bm || (om == bm && ok < bk)) { bm = om; bk = ok; }
        }
        if (lane == 0) {
            uint32_t mb = __float_as_uint(bm);
            mb = (mb & 0x80000000u) ? ~mb : (mb | 0x80000000u);
            unsigned long long key =
                ((unsigned long long)mb << 32) | (unsigned int)bk;
            atomicMin(&g_best[m0r + q], key);
        }
    }
    #pragma unroll
    for (int r = 0; r < 4; ++r) {
        bm1[r] = 3.4e38f; bm2[r] = 3.4e38f; bm3[r] = 3.4e38f;
        bi1[r] = 0; bi2[r] = 0; bi3[r] = 0;
    }
}

// ---------------- main kernel: 148 balanced CTAs over 1024 items ----------------
__global__ __launch_bounds__(THREADS, 1)
void vq_main(const float* __restrict__ enc, const float* __restrict__ cb)
{
    extern __shared__ char smem[];
    const uint32_t smem_base = smem_u32(smem);
    const int tid  = threadIdx.x;
    const int wid  = tid >> 5;
    const int lane = tid & 31;
    const int wm   = wid & 3;             // 4 warps over M (32 rows each)
    const int wn   = wid >> 2;            // 4 warps over N (32 cols each)
    const int c    = blockIdx.x;

    // contiguous linear tile range; tile T -> (qi = T>>6, kt = T&63)
    const int T0 = (c * N_ITEMS / NCTAS) * 8;
    const int T1 = ((c + 1) * N_ITEMS / NCTAS) * 8;

    // ---- B ring prologue (k-tiles for T0..T0+2; qi-independent) ----
    load_B_tile(smem_base, T0 & 63, 0, tid); CP_COMMIT();
    load_B_tile(smem_base, (T0 + 1) & 63, 1, tid); CP_COMMIT();
    load_B_tile(smem_base, (T0 + 2) & 63, 2, tid); CP_COMMIT();

    const uint32_t a_base = smem_base + SM_A
        + (wm * 32 + (lane & 15)) * ROWB + ((lane >> 4) & 1) * 16;
    const uint32_t b_base = smem_base + SM_B
        + (wn * 32 + (lane >> 4) * 8 + (lane & 7)) * ROWB + ((lane >> 3) & 1) * 16;

    uint32_t af[4][2][4];                 // A fragments [ks][i][frag]
    float bm1[4], bm2[4], bm3[4];
    int   bi1[4], bi2[4], bi3[4];
    #pragma unroll
    for (int r = 0; r < 4; ++r) {
        bm1[r] = 3.4e38f; bm2[r] = 3.4e38f; bm3[r] = 3.4e38f;
        bi1[r] = 0; bi2[r] = 0; bi3[r] = 0;
    }
    float acc[2][4][4];
    int cur_qi = -1;

    for (int T = T0; T < T1; ++T) {
        const int qi = T >> 6;
        const int kt = T & 63;

        if (qi != cur_qi) {
            if (cur_qi >= 0)
                flush_cands(smem, enc, cb, cur_qi * MT, wid, lane, wm, wn,
                            bm1, bm2, bm3, bi1, bi2, bi3);
            __syncthreads();              // safe to overwrite SM_A
            #pragma unroll
            for (int i = 0; i < 2; ++i) {
                int cc = tid + i * THREADS;
                int r = cc >> 3;
                int q = cc & 7;
                const uint4* src =
                    (const uint4*)(g_enc_bf + (size_t)(qi * MT + r) * DIMS) + q;
                *(uint4*)(smem + SM_A + r * ROWB + q * 16) = *src;
            }
            __syncthreads();
            #pragma unroll
            for (int ks = 0; ks < 4; ++ks)
                #pragma unroll
                for (int i = 0; i < 2; ++i)
                    ldsm_x4(af[ks][i], a_base + i * 16 * ROWB + ks * 32);
            cur_qi = qi;
        }

        const int stage = (T - T0) & 3;
        CP_WAIT2();                       // tile T resident
        __syncthreads();                  // prev stage fully consumed by all warps
        if (T + 3 < T1) load_B_tile(smem_base, (T + 3) & 63, (T + 3 - T0) & 3, tid);
        CP_COMMIT();

        #pragma unroll
        for (int i = 0; i < 2; ++i)
            #pragma unroll
            for (int j = 0; j < 4; ++j)
                #pragma unroll
                for (int r = 0; r < 4; ++r) acc[i][j][r] = 0.f;

        const uint32_t bs = b_base + stage * STAGE;
        #pragma unroll
        for (int ks = 0; ks < 4; ++ks) {
            uint32_t bh[4][2];
            {
                uint32_t r0[4], r1[4];
                ldsm_x4(r0, bs + ks * 32);
                ldsm_x4(r1, bs + 16 * ROWB + ks * 32);
                bh[0][0] = r0[0]; bh[0][1] = r0[1];
                bh[1][0] = r0[2]; bh[1][1] = r0[3];
                bh[2][0] = r1[0]; bh[2][1] = r1[1];
                bh[3][0] = r1[2]; bh[3][1] = r1[3];
            }
            #pragma unroll
            for (int i = 0; i < 2; ++i)
                #pragma unroll
                for (int j = 0; j < 4; ++j) mma16816(acc[i][j], af[ks][i], bh[j]);
        }

        // fused argmin epilogue (top-3 per owned query row)
        const int kb = kt * NT;
        #pragma unroll
        for (int j = 0; j < 4; ++j) {
            float2 cs = *(const float2*)(smem + SM_B + stage * STAGE + TERM_BYTES
                        + (wn * 32 + j * 8 + (lane & 3) * 2) * 4);
            const int k0 = kb + wn * 32 + j * 8 + (lane & 3) * 2;
            #pragma unroll
            for (int i = 0; i < 2; ++i) {
                #pragma unroll
                for (int h = 0; h < 2; ++h) {
                    const int ri = i * 2 + h;
                    #pragma unroll
                    for (int cc = 0; cc < 2; ++cc) {
                        float m = fmaf(-2.f, acc[i][j][h * 2 + cc], cc ? cs.y : cs.x);
                        const int k = k0 + cc;
                        if (m < bm3[ri]) {
                            if (m < bm1[ri]) {
                                bm3[ri] = bm2[ri]; bi3[ri] = bi2[ri];
                                bm2[ri] = bm1[ri]; bi2[ri] = bi1[ri];
                                bm1[ri] = m;       bi1[ri] = k;
                            } else if (m < bm2[ri]) {
                                bm3[ri] = bm2[ri]; bi3[ri] = bi2[ri];
                                bm2[ri] = m;       bi2[ri] = k;
                            } else {
                                bm3[ri] = m;       bi3[ri] = k;
                            }
                        }
                    }
                }
            }
        }
    }

    flush_cands(smem, enc, cb, cur_qi * MT, wid, lane, wm, wn,
                bm1, bm2, bm3, bi1, bi2, bi3);
}

// ---------------- gather: out[q] = codebook[key_low32] ----------------
__global__ void gather_kernel(const float* __restrict__ cb, float* __restrict__ out) {
    int idx = blockIdx.x * blockDim.x + threadIdx.x;   // one float4 of output
    int q = idx >> 4;
    int quad = idx & 15;
    int k = (int)(unsigned int)(g_best[q] & 0xFFFFFFFFULL);
    ((float4*)out)[idx] = ((const float4*)cb)[(size_t)k * 16 + quad];
}

extern "C" void kernel_launch(void* const* d_in, const int* in_sizes, int n_in,
                              void* d_out, int out_size) {
    const float* enc = (const float*)d_in[0];
    const float* cb  = (const float*)d_in[1];
    if (n_in >= 2 && in_sizes[0] == K_CB * DIMS && in_sizes[1] == N_Q * DIMS) {
        enc = (const float*)d_in[1];
        cb  = (const float*)d_in[0];
    }
    float* out = (float*)d_out;

    cudaFuncSetAttribute(vq_main, cudaFuncAttributeMaxDynamicSharedMemorySize, SMEM_TOTAL);

    prep_kernel<<<(N_Q * DIMS + K_CB * DIMS) / 4 / 256, 256>>>(enc, cb);
    csq_kernel<<<K_CB / 8, 256>>>(cb);
    vq_main<<<NCTAS, THREADS, SMEM_TOTAL>>>(enc, cb);
    gather_kernel<<<(N_Q * 16) / 256, 256>>>(cb, out);
}